// round 9
// baseline (speedup 1.0000x reference)
#include <cuda_runtime.h>
#include <stdint.h>

#define NB   8
#define NCAM 6
#define NBOX 900
#define ND   48
#define BPB  (NCAM*NBOX)            /* 5400  */
#define TOTAL_BOXES (NB*BPB)        /* 43200 */
#define MAXQ 400
#define ITERS1 6                    /* ceil(5400/1024) */
#define NBIN 512                    /* top 9 key bits */
#define HPITCH 513                  /* replica pitch (bank-conflict dodge) */

typedef unsigned long long u64;

// Scratch (fully overwritten every call -> deterministic, graph-safe)
__device__ u64 g_bitmap[TOTAL_BOXES];
__device__ u64 g_key[TOTAL_BOXES];

struct CamData {
    float f, kf, k02, k12;
    float e00,e01,e02,e03, e10,e11,e12,e13, e20,e21,e22,e23;
    float cx, cy;
};

__device__ __forceinline__ float depth_of(int dd) {
    const float step = 59.0f / 47.0f;
    if (dd == ND-1) return 60.0f;                // linspace endpoint exact
    return __fadd_rn(__fmul_rn((float)dd, step), 1.0f);
}

__device__ __forceinline__ void load_cam(const float* __restrict__ Kmat,
                                         const float* __restrict__ Emat,
                                         int cam, CamData& cd) {
    float f = Kmat[cam*16 + 0];
    cd.f   = f;
    cd.kf  = 1.0f / f;
    cd.k02 = -(400.0f * cd.kf);
    cd.k12 = -(224.0f * cd.kf);
    const float* e = Emat + cam*16;
    cd.e00=e[0];  cd.e01=e[1];  cd.e02=e[2];  cd.e03=e[3];
    cd.e10=e[4];  cd.e11=e[5];  cd.e12=e[6];  cd.e13=e[7];
    cd.e20=e[8];  cd.e21=e[9];  cd.e22=e[10]; cd.e23=e[11];
}

__device__ __forceinline__ void fwd_point(const CamData& cd, float d,
                                          float& X, float& Y, float& Z) {
    float pcx = cd.kf*(cd.cx*d) + cd.k02*d;
    float pcy = cd.kf*(cd.cy*d) + cd.k12*d;
    X = cd.e00*pcx + cd.e01*pcy + cd.e02*d + cd.e03;
    Y = cd.e10*pcx + cd.e11*pcy + cd.e12*d + cd.e13;
    Z = cd.e20*pcx + cd.e21*pcy + cd.e22*d + cd.e23;
}

// warp-aggregated compaction slot (call with ALL 32 lanes converged)
__device__ __forceinline__ int ballot_slot(bool pred, int* counter) {
    unsigned m = __ballot_sync(0xffffffffu, pred);
    if (!m) return -1;
    int lane = threadIdx.x & 31;
    int rank = __popc(m & ((1u << lane) - 1));
    int leader = __ffs(m) - 1;
    int base = 0;
    if (lane == leader) base = atomicAdd(counter, __popc(m));
    base = __shfl_sync(0xffffffffu, base, leader);
    return base + rank;
}

// ---------------------------------------------------------------------------
// K1: per-box mask bitmap + composite key. 4 lanes/box, 12 depths/lane.
// key64 = areaBits<<32 | (0x3FFF - boxIdx)<<6 | cnt   (larger = better, unique)
// (R6 version, byte-identical arithmetic)
// ---------------------------------------------------------------------------
__global__ void __launch_bounds__(256)
k_mask(const float* __restrict__ boxes,
       const float* __restrict__ Kmat,
       const float* __restrict__ Emat)
{
    int tid = blockIdx.x * blockDim.x + threadIdx.x;
    int box_gid = tid >> 2;
    int chunk   = tid & 3;
    if (box_gid >= TOTAL_BOXES) return;

    int b  = box_gid / BPB;
    int bl = box_gid % BPB;
    int c  = bl / NBOX;
    int cam = b*NCAM + c;

    float4 bx = ((const float4*)boxes)[box_gid];
    CamData cd; load_cam(Kmat, Emat, cam, cd);
    cd.cx = (bx.x + bx.z)*0.5f;
    cd.cy = (bx.y + bx.w)*0.5f;

    float area = (bx.z - bx.x)*(bx.w - bx.y);
    bool valid = (area > 5.0f) && (area < 197120.0f);

    // Einv (rigid): Rinv = R^T, tinv = -R^T t ; bottom row exact
    float i00=cd.e00, i01=cd.e10, i02=cd.e20;
    float i10=cd.e01, i11=cd.e11, i12=cd.e21;
    float i20=cd.e02, i21=cd.e12, i22=cd.e22;
    float t0=cd.e03, t1=cd.e13, t2=cd.e23;
    float ti0 = -(i00*t0 + i01*t1 + i02*t2);
    float ti1 = -(i10*t0 + i11*t1 + i12*t2);
    float ti2 = -(i20*t0 + i21*t1 + i22*t2);

    const float INV_ONE_EPS = 1.0f / (1.0f + 1e-6f);

    u64 bmp = 0ull;
    #pragma unroll
    for (int r = 0; r < 12; r++) {
        int dd = chunk*12 + r;
        float d = depth_of(dd);
        float X,Y,Z;
        fwd_point(cd, d, X, Y, Z);
        float p0 = i00*X + i01*Y + i02*Z + ti0;
        float p1 = i10*X + i11*Y + i12*Z + ti1;
        float p2 = i20*X + i21*Y + i22*Z + ti2;
        float pc0 = p0 * INV_ONE_EPS;
        float pc1 = p1 * INV_ONE_EPS;
        float pc2 = p2 * INV_ONE_EPS;
        float pih0 = cd.f*pc0 + 400.0f*pc2;
        float pih1 = cd.f*pc1 + 224.0f*pc2;
        float zd = pc2 + 1e-6f;
        float invzd = 1.0f / zd;
        float imgx = pih0 * invzd;
        float imgy = pih1 * invzd;
        float bs = fminf(fmaxf(40.0f * (10.0f * invzd), 8.0f), 200.0f);
        float half = bs * 0.5f;
        float px0 = imgx - half, py0 = imgy - half;
        float px1 = imgx + half, py1 = imgy + half;
        float xx1 = fmaxf(px0, bx.x);
        float yy1 = fmaxf(py0, bx.y);
        float xx2 = fminf(px1, bx.z);
        float yy2 = fminf(py1, bx.w);
        float inter = fmaxf(xx2-xx1, 0.0f) * fmaxf(yy2-yy1, 0.0f);
        float a1 = (px1-px0)*(py1-py0);
        float iou = inter / (a1 + area - inter + 1e-6f);   // exact: threshold-sensitive
        if ((iou > 0.05f) && valid) bmp |= (1ull << dd);
    }
    bmp |= __shfl_xor_sync(0xffffffffu, bmp, 1);
    bmp |= __shfl_xor_sync(0xffffffffu, bmp, 2);
    if (chunk == 0) {
        g_bitmap[box_gid] = bmp;
        int cnt = __popcll(bmp);
        u64 key = 0;
        if (cnt)
            key = ((u64)__float_as_uint(area) << 32)
                | ((u64)(0x3FFFu - (unsigned)bl) << 6)
                | (unsigned)cnt;
        g_key[box_gid] = key;
    }
}

// ---------------------------------------------------------------------------
// K2: per-batch selection (R6 logic, atomic-free histogram):
//   P1 load keys -> regs; per-warp private 512-bin hist via match_any+redux
//      (plain LDS/STS, zero ATOMS); warp-reduce total
//   P1b reduce 32 replicas -> hist[512]
//   P2 suffix-scan (512 bins); hist := weighted sum strictly above (sufAbove)
//   P3 winners = keys with sufAbove[bin] < MAXQ (warp-aggregated compaction)
//   P4 off = sufAbove[bin] + same-bin weighted rank; expand if off < MAXQ
//   P5 output
// ---------------------------------------------------------------------------
__global__ void __launch_bounds__(1024)
k_select(const float* __restrict__ boxes,
         const float* __restrict__ Kmat,
         const float* __restrict__ Emat,
         float* __restrict__ out, int out_size)
{
    extern __shared__ unsigned char dyn[];
    u64* swin  = (u64*)dyn;                       // 5400 * 8 = 43200
    int* whist = (int*)(dyn + BPB*8);             // 32 * 513 * 4 = 65664
    __shared__ int hist[NBIN];                    // merged -> sufAbove
    __shared__ int ssel[MAXQ];
    __shared__ int wsum[4], wrun[4];
    __shared__ int s_cnt, s_total;

    int b    = blockIdx.x;
    int tid  = threadIdx.x;
    int lane = tid & 31;
    int wid  = tid >> 5;
    if (tid == 0) { s_cnt = 0; s_total = 0; }
    // zero the 32 hist replicas (16416 ints)
    for (int i = tid; i < 32*HPITCH; i += 1024) whist[i] = 0;
    __syncthreads();

    // ---- P1: read keys once, private-hist (no atomics), total ----
    int* myhist = &whist[wid * HPITCH];
    u64 kloc[ITERS1];
    int my = 0;
    #pragma unroll
    for (int it = 0; it < ITERS1; it++) {
        int i = it*1024 + tid;
        u64 key = (i < BPB) ? g_key[b*BPB + i] : 0;
        kloc[it] = key;
        int cnt = (int)(key & 63ull);             // 0 for empty keys
        my += cnt;
        int bin = (int)(key >> 55);               // 9 bits; empty -> bin 0, w=0
        unsigned grp = __match_any_sync(0xffffffffu, bin);
        int gsum = __reduce_add_sync(grp, cnt);
        if (lane == (__ffs(grp) - 1))
            myhist[bin] += gsum;                  // leaders: distinct bins/replica
    }
    #pragma unroll
    for (int off = 16; off > 0; off >>= 1)
        my += __shfl_down_sync(0xffffffffu, my, off);
    if (lane == 0 && my) atomicAdd(&s_total, my);
    __syncthreads();

    // ---- P1b: merge replicas ----
    if (tid < NBIN) {
        int s = 0;
        #pragma unroll
        for (int r = 0; r < 32; r++) s += whist[r*HPITCH + tid];
        hist[tid] = s;
    }
    __syncthreads();
    int total  = s_total;
    int filled = min(total, MAXQ);
    bool areaOrder = (total > MAXQ);

    // ---- P2: suffix scan (512 bins, 128 threads x 4 bins) -> sufAbove ----
    if (areaOrder) {
        int h0=0,h1=0,h2=0,h3=0, run=0;
        if (tid < 128) {
            int base_bin = tid * 4;
            h0 = hist[base_bin+0]; h1 = hist[base_bin+1];
            h2 = hist[base_bin+2]; h3 = hist[base_bin+3];
            int ls = h0 + h1 + h2 + h3;
            int suf = ls;
            #pragma unroll
            for (int off = 1; off < 32; off <<= 1) {
                int v = __shfl_down_sync(0xffffffffu, suf, off);
                if (lane + off < 32) suf += v;
            }
            run = suf - ls;                       // lanes > lane, this warp
            if (lane == 0) wsum[wid] = suf;
        }
        __syncthreads();
        if (tid == 0) {
            int acc = 0;
            #pragma unroll
            for (int r = 3; r >= 0; r--) { wrun[r] = acc; acc += wsum[r]; }
        }
        __syncthreads();
        if (tid < 128) {
            int base_bin = tid * 4;
            int r = wrun[wid] + run;              // strictly above my 4 bins
            hist[base_bin+3] = r;
            hist[base_bin+2] = r + h3;
            hist[base_bin+1] = r + h3 + h2;
            hist[base_bin+0] = r + h3 + h2 + h1;
        }
        __syncthreads();
    }

    // ---- P3: winner compaction ----
    #pragma unroll
    for (int it = 0; it < ITERS1; it++) {
        u64 key = kloc[it];
        bool p;
        if (areaOrder) p = key && (hist[(int)(key >> 55)] < MAXQ);
        else           p = (key != 0);
        int slot = ballot_slot(p, &s_cnt);
        if (p) swin[slot] = key;
    }
    __syncthreads();
    int W = s_cnt;

    // ---- P4: rank + expand ----
    for (int w = tid; w < W; w += 1024) {
        u64 key = swin[w];
        int off;
        if (areaOrder) {
            int myBin = (int)(key >> 55);
            off = hist[myBin];                    // sufAbove
            for (int v = 0; v < W; v++) {
                u64 kv = swin[v];
                if (kv > key && (int)(kv >> 55) == myBin)
                    off += (int)(kv & 63ull);
            }
        } else {
            unsigned inv = (unsigned)((key >> 6) & 0x3FFFull);
            off = 0;
            for (int v = 0; v < W; v++) {
                u64 kv = swin[v];
                if (((unsigned)((kv >> 6) & 0x3FFFull)) > inv)
                    off += (int)(kv & 63ull);
            }
        }
        if (off < MAXQ) {
            int boxLocal = 0x3FFF - (int)((key >> 6) & 0x3FFFull);
            u64 bm = g_bitmap[b*BPB + boxLocal];
            int cnt  = (int)(key & 63ull);
            int take = min(cnt, MAXQ - off);
            for (int t = 0; t < take; t++) {
                int d = __ffsll((long long)bm) - 1;   // depths asc = index asc
                bm &= bm - 1;
                ssel[off + t] = (boxLocal << 6) | d;
            }
        }
    }
    __syncthreads();

    // ---- P5: output ----
    if (tid < MAXQ) {
        const float DENOM = (float)(102.400001);
        float rx, ry, rz, pm;
        if (tid < filled) {
            int v = ssel[tid];
            int boxLocal = v >> 6;
            int dd = v & 63;
            int box_gid = b*BPB + boxLocal;
            int c = boxLocal / NBOX;
            int cam = b*NCAM + c;
            float4 bx = ((const float4*)boxes)[box_gid];
            CamData cd; load_cam(Kmat, Emat, cam, cd);
            cd.cx = (bx.x + bx.z)*0.5f;
            cd.cy = (bx.y + bx.w)*0.5f;
            float d = depth_of(dd);
            float X,Y,Z; fwd_point(cd, d, X, Y, Z);
            rx = fminf(fmaxf((X + 51.2f)/DENOM, 0.0f), 1.0f);
            ry = fminf(fmaxf((Y + 51.2f)/DENOM, 0.0f), 1.0f);
            rz = fminf(fmaxf((Z + 51.2f)/DENOM, 0.0f), 1.0f);
            pm = 0.0f;
        } else {
            float pad = fminf(fmaxf(51.2f/DENOM, 0.0f), 1.0f);
            rx = ry = rz = pad;
            pm = 1.0f;
        }
        int rbase = (b*MAXQ + tid)*3;
        out[rbase + 0] = rx;
        out[rbase + 1] = ry;
        out[rbase + 2] = rz;
        if (out_size >= NB*MAXQ*4)
            out[NB*MAXQ*3 + b*MAXQ + tid] = pm;
    }
}

// ---------------------------------------------------------------------------
extern "C" void kernel_launch(void* const* d_in, const int* in_sizes, int n_in,
                              void* d_out, int out_size)
{
    const float* boxes = (const float*)d_in[0];   // (8,6,900,4)
    const float* Kmat  = (const float*)d_in[1];   // (8,6,4,4)
    const float* Emat  = (const float*)d_in[2];   // (8,6,4,4)
    float* out = (float*)d_out;

    const int smem_bytes = BPB*8 + 32*HPITCH*4;   // 43200 + 65664 = 108864
    cudaFuncSetAttribute(k_select, cudaFuncAttributeMaxDynamicSharedMemorySize,
                         smem_bytes);

    k_mask<<<(TOTAL_BOXES*4)/256, 256>>>(boxes, Kmat, Emat);
    k_select<<<NB, 1024, smem_bytes>>>(boxes, Kmat, Emat, out, out_size);
}

// round 10
// speedup vs baseline: 5.6483x; 5.6483x over previous
#include <cuda_runtime.h>
#include <stdint.h>

#define NB   8
#define NCAM 6
#define NBOX 900
#define ND   48
#define BPB  (NCAM*NBOX)            /* 5400  */
#define TOTAL_BOXES (NB*BPB)        /* 43200 */
#define MAXQ 400
#define ITERS1 6                    /* ceil(5400/1024) */
#define NBIN 4096

typedef unsigned long long u64;

// Scratch (fully overwritten every call -> deterministic, graph-safe)
__device__ u64 g_bitmap[TOTAL_BOXES];
__device__ u64 g_key[TOTAL_BOXES];

struct CamData {
    float f, kf, k02, k12;
    float e00,e01,e02,e03, e10,e11,e12,e13, e20,e21,e22,e23;
    float cx, cy;
};

__device__ __forceinline__ float depth_of(int dd) {
    const float step = 59.0f / 47.0f;
    if (dd == ND-1) return 60.0f;                // linspace endpoint exact
    return __fadd_rn(__fmul_rn((float)dd, step), 1.0f);
}

__device__ __forceinline__ void load_cam(const float* __restrict__ Kmat,
                                         const float* __restrict__ Emat,
                                         int cam, CamData& cd) {
    float f = Kmat[cam*16 + 0];
    cd.f   = f;
    cd.kf  = 1.0f / f;
    cd.k02 = -(400.0f * cd.kf);
    cd.k12 = -(224.0f * cd.kf);
    const float* e = Emat + cam*16;
    cd.e00=e[0];  cd.e01=e[1];  cd.e02=e[2];  cd.e03=e[3];
    cd.e10=e[4];  cd.e11=e[5];  cd.e12=e[6];  cd.e13=e[7];
    cd.e20=e[8];  cd.e21=e[9];  cd.e22=e[10]; cd.e23=e[11];
}

__device__ __forceinline__ void fwd_point(const CamData& cd, float d,
                                          float& X, float& Y, float& Z) {
    float pcx = cd.kf*(cd.cx*d) + cd.k02*d;
    float pcy = cd.kf*(cd.cy*d) + cd.k12*d;
    X = cd.e00*pcx + cd.e01*pcy + cd.e02*d + cd.e03;
    Y = cd.e10*pcx + cd.e11*pcy + cd.e12*d + cd.e13;
    Z = cd.e20*pcx + cd.e21*pcy + cd.e22*d + cd.e23;
}

// ---------------------------------------------------------------------------
// K1: per-box mask bitmap + composite key. 4 lanes/box, 12 depths/lane.
// key64 = areaBits<<32 | (0x3FFF - boxIdx)<<6 | cnt   (larger = better, unique)
// (R6 version, byte-identical arithmetic)
// ---------------------------------------------------------------------------
__global__ void __launch_bounds__(256)
k_mask(const float* __restrict__ boxes,
       const float* __restrict__ Kmat,
       const float* __restrict__ Emat)
{
    int tid = blockIdx.x * blockDim.x + threadIdx.x;
    int box_gid = tid >> 2;
    int chunk   = tid & 3;
    if (box_gid >= TOTAL_BOXES) return;

    int b  = box_gid / BPB;
    int bl = box_gid % BPB;
    int c  = bl / NBOX;
    int cam = b*NCAM + c;

    float4 bx = ((const float4*)boxes)[box_gid];
    CamData cd; load_cam(Kmat, Emat, cam, cd);
    cd.cx = (bx.x + bx.z)*0.5f;
    cd.cy = (bx.y + bx.w)*0.5f;

    float area = (bx.z - bx.x)*(bx.w - bx.y);
    bool valid = (area > 5.0f) && (area < 197120.0f);

    // Einv (rigid): Rinv = R^T, tinv = -R^T t ; bottom row exact
    float i00=cd.e00, i01=cd.e10, i02=cd.e20;
    float i10=cd.e01, i11=cd.e11, i12=cd.e21;
    float i20=cd.e02, i21=cd.e12, i22=cd.e22;
    float t0=cd.e03, t1=cd.e13, t2=cd.e23;
    float ti0 = -(i00*t0 + i01*t1 + i02*t2);
    float ti1 = -(i10*t0 + i11*t1 + i12*t2);
    float ti2 = -(i20*t0 + i21*t1 + i22*t2);

    const float INV_ONE_EPS = 1.0f / (1.0f + 1e-6f);

    u64 bmp = 0ull;
    #pragma unroll
    for (int r = 0; r < 12; r++) {
        int dd = chunk*12 + r;
        float d = depth_of(dd);
        float X,Y,Z;
        fwd_point(cd, d, X, Y, Z);
        float p0 = i00*X + i01*Y + i02*Z + ti0;
        float p1 = i10*X + i11*Y + i12*Z + ti1;
        float p2 = i20*X + i21*Y + i22*Z + ti2;
        float pc0 = p0 * INV_ONE_EPS;
        float pc1 = p1 * INV_ONE_EPS;
        float pc2 = p2 * INV_ONE_EPS;
        float pih0 = cd.f*pc0 + 400.0f*pc2;
        float pih1 = cd.f*pc1 + 224.0f*pc2;
        float zd = pc2 + 1e-6f;
        float invzd = 1.0f / zd;
        float imgx = pih0 * invzd;
        float imgy = pih1 * invzd;
        float bs = fminf(fmaxf(40.0f * (10.0f * invzd), 8.0f), 200.0f);
        float half = bs * 0.5f;
        float px0 = imgx - half, py0 = imgy - half;
        float px1 = imgx + half, py1 = imgy + half;
        float xx1 = fmaxf(px0, bx.x);
        float yy1 = fmaxf(py0, bx.y);
        float xx2 = fminf(px1, bx.z);
        float yy2 = fminf(py1, bx.w);
        float inter = fmaxf(xx2-xx1, 0.0f) * fmaxf(yy2-yy1, 0.0f);
        float a1 = (px1-px0)*(py1-py0);
        float iou = inter / (a1 + area - inter + 1e-6f);   // exact: threshold-sensitive
        if ((iou > 0.05f) && valid) bmp |= (1ull << dd);
    }
    bmp |= __shfl_xor_sync(0xffffffffu, bmp, 1);
    bmp |= __shfl_xor_sync(0xffffffffu, bmp, 2);
    if (chunk == 0) {
        g_bitmap[box_gid] = bmp;
        int cnt = __popcll(bmp);
        u64 key = 0;
        if (cnt)
            key = ((u64)__float_as_uint(area) << 32)
                | ((u64)(0x3FFFu - (unsigned)bl) << 6)
                | (unsigned)cnt;
        g_key[box_gid] = key;
    }
}

// ---------------------------------------------------------------------------
// K2: per-batch selection (R6 logic; single-address atomics eliminated):
//   P1 load keys -> regs; weighted 4096-bin hist (spread atomics, proven);
//      total via wsum reduction (no atomic)
//   P2 suffix-scan; hist := weighted sum strictly above (sufAbove)
//   P3 winner compaction via block scan (ZERO atomics; swin unordered - OK,
//      P4 ranks by comparison, not position)
//   P4 rank with 2 threads/winner (shfl_xor combine) + same-bin check; expand
//   P5 output
// ---------------------------------------------------------------------------
__global__ void __launch_bounds__(1024)
k_select(const float* __restrict__ boxes,
         const float* __restrict__ Kmat,
         const float* __restrict__ Emat,
         float* __restrict__ out, int out_size)
{
    extern __shared__ u64 swin[];                 // winner keys (<= 5400)
    __shared__ int hist[NBIN];                    // weighted hist -> sufAbove
    __shared__ int ssel[MAXQ];
    __shared__ int wsum[32], wrun[32];
    __shared__ int s_total, s_W;

    int b    = blockIdx.x;
    int tid  = threadIdx.x;
    int lane = tid & 31;
    int wid  = tid >> 5;
    #pragma unroll
    for (int j = 0; j < NBIN/1024; j++) hist[j*1024 + tid] = 0;
    __syncthreads();

    // ---- P1: read keys once, spread-bin hist atomics, total via scan ----
    u64 kloc[ITERS1];
    int my = 0;
    #pragma unroll
    for (int it = 0; it < ITERS1; it++) {
        int i = it*1024 + tid;
        u64 key = (i < BPB) ? g_key[b*BPB + i] : 0;
        kloc[it] = key;
        if (key) {
            my += (int)(key & 63ull);
            atomicAdd(&hist[(int)(key >> 52)], (int)(key & 63ull));
        }
    }
    #pragma unroll
    for (int off = 16; off > 0; off >>= 1)
        my += __shfl_down_sync(0xffffffffu, my, off);
    if (lane == 0) wsum[wid] = my;
    __syncthreads();
    if (tid == 0) {
        int t = 0;
        #pragma unroll
        for (int r = 0; r < 32; r++) t += wsum[r];
        s_total = t;
    }
    __syncthreads();
    int total  = s_total;
    int filled = min(total, MAXQ);
    bool areaOrder = (total > MAXQ);

    // ---- P2: suffix scan -> hist becomes sufAbove (exclusive, from above) --
    if (areaOrder) {
        int base_bin = tid * 4;
        int h0 = hist[base_bin+0], h1 = hist[base_bin+1];
        int h2 = hist[base_bin+2], h3 = hist[base_bin+3];
        int ls = h0 + h1 + h2 + h3;
        int suf = ls;
        #pragma unroll
        for (int off = 1; off < 32; off <<= 1) {
            int v = __shfl_down_sync(0xffffffffu, suf, off);
            if (lane + off < 32) suf += v;
        }
        int run = suf - ls;                       // lanes > lane, this warp
        if (lane == 0) wsum[wid] = suf;
        __syncthreads();
        if (tid == 0) {
            int acc = 0;
            #pragma unroll
            for (int r = 31; r >= 0; r--) { wrun[r] = acc; acc += wsum[r]; }
        }
        __syncthreads();
        int r = wrun[wid] + run;                  // strictly above my 4 bins
        hist[base_bin+3] = r;
        hist[base_bin+2] = r + h3;
        hist[base_bin+1] = r + h3 + h2;
        hist[base_bin+0] = r + h3 + h2 + h1;
        __syncthreads();
    }

    // ---- P3: winner compaction via block scan (no atomics) ----
    bool pw[ITERS1];
    int mycnt = 0;
    #pragma unroll
    for (int it = 0; it < ITERS1; it++) {
        u64 key = kloc[it];
        bool p;
        if (areaOrder) p = key && (hist[(int)(key >> 52)] < MAXQ);
        else           p = (key != 0);
        pw[it] = p;
        mycnt += p ? 1 : 0;
    }
    int incl = mycnt;
    #pragma unroll
    for (int off = 1; off < 32; off <<= 1) {
        int v = __shfl_up_sync(0xffffffffu, incl, off);
        if (lane >= off) incl += v;
    }
    int excl = incl - mycnt;
    if (lane == 31) wsum[wid] = incl;             // warp total
    __syncthreads();
    if (tid == 0) {
        int acc = 0;
        #pragma unroll
        for (int r = 0; r < 32; r++) { wrun[r] = acc; acc += wsum[r]; }
        s_W = acc;
    }
    __syncthreads();
    int slot = wrun[wid] + excl;
    #pragma unroll
    for (int it = 0; it < ITERS1; it++) {
        if (pw[it]) swin[slot++] = kloc[it];
    }
    __syncthreads();
    int W = s_W;

    // ---- P4: rank (2 threads per winner, shfl_xor combine) + expand ----
    for (int base = 0; base < 2*W; base += 1024) {
        int idx = base + tid;
        bool vld = (idx < 2*W);
        int w   = vld ? (idx >> 1) : 0;
        int par = idx & 1;
        u64 key = swin[w];                        // safe: w<W when vld, else w=0 (W>0 here)
        int part = 0;
        if (vld) {
            if (areaOrder) {
                int myBin = (int)(key >> 52);
                for (int v = par; v < W; v += 2) {
                    u64 kv = swin[v];
                    if (kv > key && (int)(kv >> 52) == myBin)
                        part += (int)(kv & 63ull);
                }
            } else {
                unsigned inv = (unsigned)((key >> 6) & 0x3FFFull);
                for (int v = par; v < W; v += 2) {
                    u64 kv = swin[v];
                    if (((unsigned)((kv >> 6) & 0x3FFFull)) > inv)
                        part += (int)(kv & 63ull);
                }
            }
        }
        int other = __shfl_xor_sync(0xffffffffu, part, 1);
        if (vld && par == 0) {
            int off = part + other;
            if (areaOrder) off += hist[(int)(key >> 52)];   // sufAbove
            if (off < MAXQ) {
                int boxLocal = 0x3FFF - (int)((key >> 6) & 0x3FFFull);
                u64 bm = g_bitmap[b*BPB + boxLocal];
                int cnt  = (int)(key & 63ull);
                int take = min(cnt, MAXQ - off);
                for (int t = 0; t < take; t++) {
                    int d = __ffsll((long long)bm) - 1;   // depths asc = index asc
                    bm &= bm - 1;
                    ssel[off + t] = (boxLocal << 6) | d;
                }
            }
        }
    }
    __syncthreads();

    // ---- P5: output ----
    if (tid < MAXQ) {
        const float DENOM = (float)(102.400001);
        float rx, ry, rz, pm;
        if (tid < filled) {
            int v = ssel[tid];
            int boxLocal = v >> 6;
            int dd = v & 63;
            int box_gid = b*BPB + boxLocal;
            int c = boxLocal / NBOX;
            int cam = b*NCAM + c;
            float4 bx = ((const float4*)boxes)[box_gid];
            CamData cd; load_cam(Kmat, Emat, cam, cd);
            cd.cx = (bx.x + bx.z)*0.5f;
            cd.cy = (bx.y + bx.w)*0.5f;
            float d = depth_of(dd);
            float X,Y,Z; fwd_point(cd, d, X, Y, Z);
            rx = fminf(fmaxf((X + 51.2f)/DENOM, 0.0f), 1.0f);
            ry = fminf(fmaxf((Y + 51.2f)/DENOM, 0.0f), 1.0f);
            rz = fminf(fmaxf((Z + 51.2f)/DENOM, 0.0f), 1.0f);
            pm = 0.0f;
        } else {
            float pad = fminf(fmaxf(51.2f/DENOM, 0.0f), 1.0f);
            rx = ry = rz = pad;
            pm = 1.0f;
        }
        int rbase = (b*MAXQ + tid)*3;
        out[rbase + 0] = rx;
        out[rbase + 1] = ry;
        out[rbase + 2] = rz;
        if (out_size >= NB*MAXQ*4)
            out[NB*MAXQ*3 + b*MAXQ + tid] = pm;
    }
}

// ---------------------------------------------------------------------------
extern "C" void kernel_launch(void* const* d_in, const int* in_sizes, int n_in,
                              void* d_out, int out_size)
{
    const float* boxes = (const float*)d_in[0];   // (8,6,900,4)
    const float* Kmat  = (const float*)d_in[1];   // (8,6,4,4)
    const float* Emat  = (const float*)d_in[2];   // (8,6,4,4)
    float* out = (float*)d_out;

    const int smem_bytes = BPB * 8;               // 43200 B (swin)
    cudaFuncSetAttribute(k_select, cudaFuncAttributeMaxDynamicSharedMemorySize,
                         smem_bytes);

    k_mask<<<(TOTAL_BOXES*4)/256, 256>>>(boxes, Kmat, Emat);
    k_select<<<NB, 1024, smem_bytes>>>(boxes, Kmat, Emat, out, out_size);
}

// round 11
// speedup vs baseline: 5.6578x; 1.0017x over previous
#include <cuda_runtime.h>
#include <stdint.h>

#define NB   8
#define NCAM 6
#define NBOX 900
#define ND   48
#define BPB  (NCAM*NBOX)            /* 5400  */
#define TOTAL_BOXES (NB*BPB)        /* 43200 */
#define MAXQ 400
#define ITERS1 6                    /* ceil(5400/1024) */
#define NBIN 4096

typedef unsigned long long u64;

// Scratch (fully overwritten every call -> deterministic, graph-safe)
__device__ u64 g_bitmap[TOTAL_BOXES];
__device__ u64 g_key[TOTAL_BOXES];

struct CamData {
    float f, kf, k02, k12;
    float e00,e01,e02,e03, e10,e11,e12,e13, e20,e21,e22,e23;
    float cx, cy;
};

__device__ __forceinline__ float depth_of(int dd) {
    const float step = 59.0f / 47.0f;
    if (dd == ND-1) return 60.0f;                // linspace endpoint exact
    return __fadd_rn(__fmul_rn((float)dd, step), 1.0f);
}

__device__ __forceinline__ void load_cam(const float* __restrict__ Kmat,
                                         const float* __restrict__ Emat,
                                         int cam, CamData& cd) {
    float f = Kmat[cam*16 + 0];
    cd.f   = f;
    cd.kf  = 1.0f / f;
    cd.k02 = -(400.0f * cd.kf);
    cd.k12 = -(224.0f * cd.kf);
    const float* e = Emat + cam*16;
    cd.e00=e[0];  cd.e01=e[1];  cd.e02=e[2];  cd.e03=e[3];
    cd.e10=e[4];  cd.e11=e[5];  cd.e12=e[6];  cd.e13=e[7];
    cd.e20=e[8];  cd.e21=e[9];  cd.e22=e[10]; cd.e23=e[11];
}

__device__ __forceinline__ void fwd_point(const CamData& cd, float d,
                                          float& X, float& Y, float& Z) {
    float pcx = cd.kf*(cd.cx*d) + cd.k02*d;
    float pcy = cd.kf*(cd.cy*d) + cd.k12*d;
    X = cd.e00*pcx + cd.e01*pcy + cd.e02*d + cd.e03;
    Y = cd.e10*pcx + cd.e11*pcy + cd.e12*d + cd.e13;
    Z = cd.e20*pcx + cd.e21*pcy + cd.e22*d + cd.e23;
}

// ---------------------------------------------------------------------------
// K1: per-box mask bitmap + composite key. 4 lanes/box, 12 depths/lane.
// key64 = areaBits<<32 | (0x3FFF - boxIdx)<<6 | cnt   (larger = better, unique)
// (R6/R10 version, byte-identical arithmetic)
// ---------------------------------------------------------------------------
__global__ void __launch_bounds__(256)
k_mask(const float* __restrict__ boxes,
       const float* __restrict__ Kmat,
       const float* __restrict__ Emat)
{
    int tid = blockIdx.x * blockDim.x + threadIdx.x;
    int box_gid = tid >> 2;
    int chunk   = tid & 3;
    if (box_gid >= TOTAL_BOXES) return;

    int b  = box_gid / BPB;
    int bl = box_gid % BPB;
    int c  = bl / NBOX;
    int cam = b*NCAM + c;

    float4 bx = ((const float4*)boxes)[box_gid];
    CamData cd; load_cam(Kmat, Emat, cam, cd);
    cd.cx = (bx.x + bx.z)*0.5f;
    cd.cy = (bx.y + bx.w)*0.5f;

    float area = (bx.z - bx.x)*(bx.w - bx.y);
    bool valid = (area > 5.0f) && (area < 197120.0f);

    // Einv (rigid): Rinv = R^T, tinv = -R^T t ; bottom row exact
    float i00=cd.e00, i01=cd.e10, i02=cd.e20;
    float i10=cd.e01, i11=cd.e11, i12=cd.e21;
    float i20=cd.e02, i21=cd.e12, i22=cd.e22;
    float t0=cd.e03, t1=cd.e13, t2=cd.e23;
    float ti0 = -(i00*t0 + i01*t1 + i02*t2);
    float ti1 = -(i10*t0 + i11*t1 + i12*t2);
    float ti2 = -(i20*t0 + i21*t1 + i22*t2);

    const float INV_ONE_EPS = 1.0f / (1.0f + 1e-6f);

    u64 bmp = 0ull;
    #pragma unroll
    for (int r = 0; r < 12; r++) {
        int dd = chunk*12 + r;
        float d = depth_of(dd);
        float X,Y,Z;
        fwd_point(cd, d, X, Y, Z);
        float p0 = i00*X + i01*Y + i02*Z + ti0;
        float p1 = i10*X + i11*Y + i12*Z + ti1;
        float p2 = i20*X + i21*Y + i22*Z + ti2;
        float pc0 = p0 * INV_ONE_EPS;
        float pc1 = p1 * INV_ONE_EPS;
        float pc2 = p2 * INV_ONE_EPS;
        float pih0 = cd.f*pc0 + 400.0f*pc2;
        float pih1 = cd.f*pc1 + 224.0f*pc2;
        float zd = pc2 + 1e-6f;
        float invzd = 1.0f / zd;
        float imgx = pih0 * invzd;
        float imgy = pih1 * invzd;
        float bs = fminf(fmaxf(40.0f * (10.0f * invzd), 8.0f), 200.0f);
        float half = bs * 0.5f;
        float px0 = imgx - half, py0 = imgy - half;
        float px1 = imgx + half, py1 = imgy + half;
        float xx1 = fmaxf(px0, bx.x);
        float yy1 = fmaxf(py0, bx.y);
        float xx2 = fminf(px1, bx.z);
        float yy2 = fminf(py1, bx.w);
        float inter = fmaxf(xx2-xx1, 0.0f) * fmaxf(yy2-yy1, 0.0f);
        float a1 = (px1-px0)*(py1-py0);
        float iou = inter / (a1 + area - inter + 1e-6f);   // exact: threshold-sensitive
        if ((iou > 0.05f) && valid) bmp |= (1ull << dd);
    }
    bmp |= __shfl_xor_sync(0xffffffffu, bmp, 1);
    bmp |= __shfl_xor_sync(0xffffffffu, bmp, 2);
    if (chunk == 0) {
        g_bitmap[box_gid] = bmp;
        int cnt = __popcll(bmp);
        u64 key = 0;
        if (cnt)
            key = ((u64)__float_as_uint(area) << 32)
                | ((u64)(0x3FFFu - (unsigned)bl) << 6)
                | (unsigned)cnt;
        g_key[box_gid] = key;
    }
}

// ---------------------------------------------------------------------------
// K2: per-batch selection (R10 logic + BIN-SEGMENTED rank):
//   P1  keys -> regs; weighted 4096-bin hist (spread atomics); total via scan
//   P2  suffix-scan; hist := weighted sum strictly above (sufAbove)
//   P3a winner predicate; count winners per bin into cnt2 (spread atomics)
//   P3b exclusive scan of cnt2 -> seg (segment starts); cnt2 := cursor
//   P3c place winners bin-grouped into swin via cursor atomics
//   P4  per-winner rank scans ONLY its bin segment; off = sufAbove + segrank
//   P5  output
//   (!areaOrder path: R10's validated compaction + rank, verbatim)
// ---------------------------------------------------------------------------
__global__ void __launch_bounds__(1024)
k_select(const float* __restrict__ boxes,
         const float* __restrict__ Kmat,
         const float* __restrict__ Emat,
         float* __restrict__ out, int out_size)
{
    extern __shared__ unsigned char dyn[];
    u64* swin = (u64*)dyn;                        // 5400 * 8
    int* hist = (int*)(dyn + BPB*8);              // 4096 * 4
    int* seg  = hist + NBIN;                      // 4096 * 4
    int* cnt2 = seg  + NBIN;                      // 4096 * 4
    __shared__ int ssel[MAXQ];
    __shared__ int wsum[32], wrun[32];
    __shared__ int s_total, s_W;

    int b    = blockIdx.x;
    int tid  = threadIdx.x;
    int lane = tid & 31;
    int wid  = tid >> 5;
    #pragma unroll
    for (int j = 0; j < NBIN/1024; j++) {
        hist[j*1024 + tid] = 0;
        cnt2[j*1024 + tid] = 0;
    }
    __syncthreads();

    // ---- P1: read keys once, spread-bin hist atomics, total via scan ----
    u64 kloc[ITERS1];
    int my = 0;
    #pragma unroll
    for (int it = 0; it < ITERS1; it++) {
        int i = it*1024 + tid;
        u64 key = (i < BPB) ? g_key[b*BPB + i] : 0;
        kloc[it] = key;
        if (key) {
            my += (int)(key & 63ull);
            atomicAdd(&hist[(int)(key >> 52)], (int)(key & 63ull));
        }
    }
    #pragma unroll
    for (int off = 16; off > 0; off >>= 1)
        my += __shfl_down_sync(0xffffffffu, my, off);
    if (lane == 0) wsum[wid] = my;
    __syncthreads();
    if (tid == 0) {
        int t = 0;
        #pragma unroll
        for (int r = 0; r < 32; r++) t += wsum[r];
        s_total = t;
    }
    __syncthreads();
    int total  = s_total;
    int filled = min(total, MAXQ);
    bool areaOrder = (total > MAXQ);

    if (areaOrder) {
        // ---- P2: suffix scan -> hist := sufAbove (exclusive, from above) ----
        {
            int base_bin = tid * 4;
            int h0 = hist[base_bin+0], h1 = hist[base_bin+1];
            int h2 = hist[base_bin+2], h3 = hist[base_bin+3];
            int ls = h0 + h1 + h2 + h3;
            int suf = ls;
            #pragma unroll
            for (int off = 1; off < 32; off <<= 1) {
                int v = __shfl_down_sync(0xffffffffu, suf, off);
                if (lane + off < 32) suf += v;
            }
            int run = suf - ls;                   // lanes > lane, this warp
            if (lane == 0) wsum[wid] = suf;
            __syncthreads();
            if (tid == 0) {
                int acc = 0;
                #pragma unroll
                for (int r = 31; r >= 0; r--) { wrun[r] = acc; acc += wsum[r]; }
            }
            __syncthreads();
            int r = wrun[wid] + run;              // strictly above my 4 bins
            hist[base_bin+3] = r;
            hist[base_bin+2] = r + h3;
            hist[base_bin+1] = r + h3 + h2;
            hist[base_bin+0] = r + h3 + h2 + h1;
            __syncthreads();
        }

        // ---- P3a: winner predicate + per-bin winner counts ----
        bool pw[ITERS1];
        #pragma unroll
        for (int it = 0; it < ITERS1; it++) {
            u64 key = kloc[it];
            bool p = key && (hist[(int)(key >> 52)] < MAXQ);
            pw[it] = p;
            if (p) atomicAdd(&cnt2[(int)(key >> 52)], 1);
        }
        __syncthreads();

        // ---- P3b: exclusive prefix scan of cnt2 -> seg; cnt2 := cursor ----
        {
            int base_bin = tid * 4;
            int c0 = cnt2[base_bin+0], c1 = cnt2[base_bin+1];
            int c2 = cnt2[base_bin+2], c3 = cnt2[base_bin+3];
            int ls = c0 + c1 + c2 + c3;
            int incl = ls;
            #pragma unroll
            for (int off = 1; off < 32; off <<= 1) {
                int v = __shfl_up_sync(0xffffffffu, incl, off);
                if (lane >= off) incl += v;
            }
            int excl = incl - ls;                 // lanes < lane, this warp
            if (lane == 31) wsum[wid] = incl;
            __syncthreads();
            if (tid == 0) {
                int acc = 0;
                #pragma unroll
                for (int r = 0; r < 32; r++) { wrun[r] = acc; acc += wsum[r]; }
                s_W = acc;
            }
            __syncthreads();
            int base = wrun[wid] + excl;
            seg[base_bin+0] = base;
            seg[base_bin+1] = base + c0;
            seg[base_bin+2] = base + c0 + c1;
            seg[base_bin+3] = base + c0 + c1 + c2;
            cnt2[base_bin+0] = base;
            cnt2[base_bin+1] = base + c0;
            cnt2[base_bin+2] = base + c0 + c1;
            cnt2[base_bin+3] = base + c0 + c1 + c2;
            __syncthreads();
        }
        int W = s_W;

        // ---- P3c: place winners bin-grouped ----
        #pragma unroll
        for (int it = 0; it < ITERS1; it++) {
            if (pw[it]) {
                u64 key = kloc[it];
                int slot = atomicAdd(&cnt2[(int)(key >> 52)], 1);
                swin[slot] = key;
            }
        }
        __syncthreads();

        // ---- P4: bin-segmented rank + expand ----
        for (int w = tid; w < W; w += 1024) {
            u64 key = swin[w];
            int myBin = (int)(key >> 52);
            int off = hist[myBin];                // sufAbove
            int lo = seg[myBin], hi = cnt2[myBin];
            for (int v = lo; v < hi; v++) {
                u64 kv = swin[v];
                if (kv > key) off += (int)(kv & 63ull);
            }
            if (off < MAXQ) {
                int boxLocal = 0x3FFF - (int)((key >> 6) & 0x3FFFull);
                u64 bm = g_bitmap[b*BPB + boxLocal];
                int cnt  = (int)(key & 63ull);
                int take = min(cnt, MAXQ - off);
                for (int t = 0; t < take; t++) {
                    int d = __ffsll((long long)bm) - 1;   // depths asc = index asc
                    bm &= bm - 1;
                    ssel[off + t] = (boxLocal << 6) | d;
                }
            }
        }
    } else {
        // ================= !areaOrder fallback (R10 verbatim) ==============
        bool pw[ITERS1];
        int mycnt = 0;
        #pragma unroll
        for (int it = 0; it < ITERS1; it++) {
            bool p = (kloc[it] != 0);
            pw[it] = p;
            mycnt += p ? 1 : 0;
        }
        int incl = mycnt;
        #pragma unroll
        for (int off = 1; off < 32; off <<= 1) {
            int v = __shfl_up_sync(0xffffffffu, incl, off);
            if (lane >= off) incl += v;
        }
        int excl = incl - mycnt;
        if (lane == 31) wsum[wid] = incl;
        __syncthreads();
        if (tid == 0) {
            int acc = 0;
            #pragma unroll
            for (int r = 0; r < 32; r++) { wrun[r] = acc; acc += wsum[r]; }
            s_W = acc;
        }
        __syncthreads();
        int slot = wrun[wid] + excl;
        #pragma unroll
        for (int it = 0; it < ITERS1; it++) {
            if (pw[it]) swin[slot++] = kloc[it];
        }
        __syncthreads();
        int W = s_W;

        for (int w = tid; w < W; w += 1024) {
            u64 key = swin[w];
            unsigned inv = (unsigned)((key >> 6) & 0x3FFFull);
            int off = 0;
            for (int v = 0; v < W; v++) {
                u64 kv = swin[v];
                if (((unsigned)((kv >> 6) & 0x3FFFull)) > inv)
                    off += (int)(kv & 63ull);
            }
            if (off < MAXQ) {
                int boxLocal = 0x3FFF - (int)inv;
                u64 bm = g_bitmap[b*BPB + boxLocal];
                int cnt  = (int)(key & 63ull);
                int take = min(cnt, MAXQ - off);
                for (int t = 0; t < take; t++) {
                    int d = __ffsll((long long)bm) - 1;
                    bm &= bm - 1;
                    ssel[off + t] = (boxLocal << 6) | d;
                }
            }
        }
    }
    __syncthreads();

    // ---- P5: output ----
    if (tid < MAXQ) {
        const float DENOM = (float)(102.400001);
        float rx, ry, rz, pm;
        if (tid < filled) {
            int v = ssel[tid];
            int boxLocal = v >> 6;
            int dd = v & 63;
            int box_gid = b*BPB + boxLocal;
            int c = boxLocal / NBOX;
            int cam = b*NCAM + c;
            float4 bx = ((const float4*)boxes)[box_gid];
            CamData cd; load_cam(Kmat, Emat, cam, cd);
            cd.cx = (bx.x + bx.z)*0.5f;
            cd.cy = (bx.y + bx.w)*0.5f;
            float d = depth_of(dd);
            float X,Y,Z; fwd_point(cd, d, X, Y, Z);
            rx = fminf(fmaxf((X + 51.2f)/DENOM, 0.0f), 1.0f);
            ry = fminf(fmaxf((Y + 51.2f)/DENOM, 0.0f), 1.0f);
            rz = fminf(fmaxf((Z + 51.2f)/DENOM, 0.0f), 1.0f);
            pm = 0.0f;
        } else {
            float pad = fminf(fmaxf(51.2f/DENOM, 0.0f), 1.0f);
            rx = ry = rz = pad;
            pm = 1.0f;
        }
        int rbase = (b*MAXQ + tid)*3;
        out[rbase + 0] = rx;
        out[rbase + 1] = ry;
        out[rbase + 2] = rz;
        if (out_size >= NB*MAXQ*4)
            out[NB*MAXQ*3 + b*MAXQ + tid] = pm;
    }
}

// ---------------------------------------------------------------------------
extern "C" void kernel_launch(void* const* d_in, const int* in_sizes, int n_in,
                              void* d_out, int out_size)
{
    const float* boxes = (const float*)d_in[0];   // (8,6,900,4)
    const float* Kmat  = (const float*)d_in[1];   // (8,6,4,4)
    const float* Emat  = (const float*)d_in[2];   // (8,6,4,4)
    float* out = (float*)d_out;

    const int smem_bytes = BPB*8 + 3*NBIN*4;      // 43200 + 49152 = 92352
    cudaFuncSetAttribute(k_select, cudaFuncAttributeMaxDynamicSharedMemorySize,
                         smem_bytes);

    k_mask<<<(TOTAL_BOXES*4)/256, 256>>>(boxes, Kmat, Emat);
    k_select<<<NB, 1024, smem_bytes>>>(boxes, Kmat, Emat, out, out_size);
}